// round 2
// baseline (speedup 1.0000x reference)
#include <cuda_runtime.h>

#define THREADS 256
#define TB 32          // batch elements per CTA
#define MROWS 96       // token rows per CTA (TB*3)
#define LDA 104        // smem row stride for activations
#define DM 100
#define DIN 72
#define FFD 512
#define FC 64          // FFN chunk
#define NLAYERS 8
#define NCLS 40
#define SD 300

#define OFF_X 0
#define OFF_Q 9984
#define OFF_K 19968
#define OFF_V 29952
#define OFF_W 39936
#define SMEM_FLOATS 52096   // 208,384 bytes dynamic smem

#define SW_LDW 101
#define SW2_LDW 67
#define WF_LDW 303

// Copy a weight block (row-major [rows x cols]) into shared with row stride ldw,
// zero-padding rows up to prows so the GEMM can load unconditionally.
__device__ __forceinline__ void stage_w(float* dst, int ldw, const float* __restrict__ src,
                                        int sstride, int rows, int cols, int prows) {
  const int total = prows * cols;
  for (int idx = threadIdx.x; idx < total; idx += THREADS) {
    int r = idx / cols;
    int c = idx - r * cols;
    dst[r * ldw + c] = (r < rows) ? src[r * sstride + c] : 0.0f;
  }
}

// C[m][n] += sum_k A[m][k] * W[n][k]; 256 threads as 16x16 grid,
// each thread owns rows {tm,tm+16,...,tm+80} x cols {tn,tn+16,...}.
template <int NC>
__device__ __forceinline__ void gemm_acc(const float* __restrict__ A, int lda,
                                         const float* __restrict__ W, int ldw,
                                         int K, float (&acc)[6][NC]) {
  const int tn = threadIdx.x & 15;
  const int tm = threadIdx.x >> 4;
  const float* a0 = A + tm * lda;
  const float* w0 = W + tn * ldw;
#pragma unroll 4
  for (int k = 0; k < K; k++) {
    float a[6];
#pragma unroll
    for (int r = 0; r < 6; r++) a[r] = a0[r * 16 * lda + k];
#pragma unroll
    for (int c = 0; c < NC; c++) {
      float w = w0[c * 16 * ldw + k];
#pragma unroll
      for (int r = 0; r < 6; r++) acc[r][c] = fmaf(a[r], w, acc[r][c]);
    }
  }
}

__device__ __forceinline__ void layernorm_rows(const float* __restrict__ src,
                                               float* __restrict__ dst,
                                               const float* __restrict__ g,
                                               const float* __restrict__ b) {
  const int tid = threadIdx.x;
  if (tid < MROWS) {
    const float* y = src + tid * LDA;
    float m = 0.f;
#pragma unroll 4
    for (int d = 0; d < DM; d++) m += y[d];
    m *= (1.0f / DM);
    float v = 0.f;
#pragma unroll 4
    for (int d = 0; d < DM; d++) { float t = y[d] - m; v = fmaf(t, t, v); }
    v *= (1.0f / DM);
    float inv = rsqrtf(v + 1e-5f);
    float* o = dst + tid * LDA;
#pragma unroll 4
    for (int d = 0; d < DM; d++)
      o[d] = (y[d] - m) * inv * __ldg(g + d) + __ldg(b + d);
  }
}

__global__ void __launch_bounds__(THREADS, 1)
geomapnet_kernel(const float* __restrict__ x,
                 const float* __restrict__ We, const float* __restrict__ be,
                 const float* __restrict__ pe,
                 const float* __restrict__ Wq, const float* __restrict__ bq,
                 const float* __restrict__ Wk, const float* __restrict__ bk,
                 const float* __restrict__ Wv, const float* __restrict__ bv,
                 const float* __restrict__ Wo, const float* __restrict__ bo,
                 const float* __restrict__ ln1g, const float* __restrict__ ln1b,
                 const float* __restrict__ W1, const float* __restrict__ b1,
                 const float* __restrict__ W2, const float* __restrict__ b2,
                 const float* __restrict__ ln2g, const float* __restrict__ ln2b,
                 const float* __restrict__ Wf, const float* __restrict__ bf,
                 float* __restrict__ out)
{
  extern __shared__ float smem[];
  float* sX = smem + OFF_X;   // [96][104] residual-stream activations
  float* sQ = smem + OFF_Q;   // [96][104] Q / ctx / FFN hidden chunk
  float* sK = smem + OFF_K;   // [96][104] K / pre-LN scratch
  float* sV = smem + OFF_V;   // [96][104] V
  float* sW = smem + OFF_W;   // weight staging, 12160 floats

  const int tid = threadIdx.x;
  const int tn = tid & 15;
  const int tm = tid >> 4;
  const int rowbase = blockIdx.x * MROWS;

  // ---------------- embedding: X = x @ We^T + be + pe ----------------
  for (int idx = tid; idx < MROWS * DIN; idx += THREADS) {
    int r = idx / DIN, c = idx - r * DIN;
    sQ[r * LDA + c] = x[(rowbase + r) * DIN + c];
  }
  stage_w(sW, SW_LDW, We, DIN, DM, DIN, 112);
  __syncthreads();
  {
    float acc[6][7];
#pragma unroll
    for (int r = 0; r < 6; r++)
#pragma unroll
      for (int c = 0; c < 7; c++) acc[r][c] = 0.f;
    gemm_acc<7>(sQ, LDA, sW, SW_LDW, DIN, acc);
#pragma unroll
    for (int c = 0; c < 7; c++) {
      int n = tn + 16 * c;
      if (n < DM) {
        float bias = __ldg(be + n);
#pragma unroll
        for (int r = 0; r < 6; r++) {
          int m = tm + 16 * r;
          sX[m * LDA + n] = acc[r][c] + bias + __ldg(pe + (m % 3) * DM + n);
        }
      }
    }
  }
  __syncthreads();

  // ---------------- encoder layers ----------------
  for (int li = 0; li < NLAYERS; li++) {
    const float* Wq_i = Wq + li * DM * DM;
    const float* Wk_i = Wk + li * DM * DM;
    const float* Wv_i = Wv + li * DM * DM;
    const float* Wo_i = Wo + li * DM * DM;
    const float* bq_i = bq + li * DM;
    const float* bk_i = bk + li * DM;
    const float* bv_i = bv + li * DM;
    const float* bo_i = bo + li * DM;

    // ---- Q projection ----
    stage_w(sW, SW_LDW, Wq_i, DM, DM, DM, 112);
    __syncthreads();
    {
      float acc[6][7];
#pragma unroll
      for (int r = 0; r < 6; r++)
#pragma unroll
        for (int c = 0; c < 7; c++) acc[r][c] = 0.f;
      gemm_acc<7>(sX, LDA, sW, SW_LDW, DM, acc);
#pragma unroll
      for (int c = 0; c < 7; c++) {
        int n = tn + 16 * c;
        if (n < DM) {
          float bias = __ldg(bq_i + n);
#pragma unroll
          for (int r = 0; r < 6; r++) sQ[(tm + 16 * r) * LDA + n] = acc[r][c] + bias;
        }
      }
    }
    __syncthreads();

    // ---- K projection ----
    stage_w(sW, SW_LDW, Wk_i, DM, DM, DM, 112);
    __syncthreads();
    {
      float acc[6][7];
#pragma unroll
      for (int r = 0; r < 6; r++)
#pragma unroll
        for (int c = 0; c < 7; c++) acc[r][c] = 0.f;
      gemm_acc<7>(sX, LDA, sW, SW_LDW, DM, acc);
#pragma unroll
      for (int c = 0; c < 7; c++) {
        int n = tn + 16 * c;
        if (n < DM) {
          float bias = __ldg(bk_i + n);
#pragma unroll
          for (int r = 0; r < 6; r++) sK[(tm + 16 * r) * LDA + n] = acc[r][c] + bias;
        }
      }
    }
    __syncthreads();

    // ---- V projection ----
    stage_w(sW, SW_LDW, Wv_i, DM, DM, DM, 112);
    __syncthreads();
    {
      float acc[6][7];
#pragma unroll
      for (int r = 0; r < 6; r++)
#pragma unroll
        for (int c = 0; c < 7; c++) acc[r][c] = 0.f;
      gemm_acc<7>(sX, LDA, sW, SW_LDW, DM, acc);
#pragma unroll
      for (int c = 0; c < 7; c++) {
        int n = tn + 16 * c;
        if (n < DM) {
          float bias = __ldg(bv_i + n);
#pragma unroll
          for (int r = 0; r < 6; r++) sV[(tm + 16 * r) * LDA + n] = acc[r][c] + bias;
        }
      }
    }
    __syncthreads();

    // ---- attention (flat row-major head split: head h = flat[h*30 .. h*30+30)) ----
    for (int task = tid; task < TB * 10; task += THREADS) {
      int e = task / 10;
      int h = task - e * 10;
      const int base = h * 30;
      const float* Qe = sQ + (3 * e) * LDA;
      const float* Ke = sK + (3 * e) * LDA;
      const float* Ve = sV + (3 * e) * LDA;
      float q[30], kk[30], vv[30];
#pragma unroll
      for (int j = 0; j < 30; j++) {
        int f = base + j;
        int s = f / 100;
        int d = f - s * 100;
        int off = s * LDA + d;
        q[j] = Qe[off];
        kk[j] = Ke[off];
        vv[j] = Ve[off];
      }
      const float scale = 0.3162277660168379f;  // 10^-0.5
      float att[3][3];
#pragma unroll
      for (int a2 = 0; a2 < 3; a2++) {
        float mx = -1e30f;
#pragma unroll
        for (int b2 = 0; b2 < 3; b2++) {
          float s2 = 0.f;
#pragma unroll
          for (int d3 = 0; d3 < 10; d3++) s2 = fmaf(q[a2 * 10 + d3], kk[b2 * 10 + d3], s2);
          att[a2][b2] = s2 * scale;
          mx = fmaxf(mx, att[a2][b2]);
        }
        float sum = 0.f;
#pragma unroll
        for (int b2 = 0; b2 < 3; b2++) { att[a2][b2] = __expf(att[a2][b2] - mx); sum += att[a2][b2]; }
        float inv = 1.f / sum;
#pragma unroll
        for (int b2 = 0; b2 < 3; b2++) att[a2][b2] *= inv;
      }
      float* Qw = sQ + (3 * e) * LDA;
#pragma unroll
      for (int a2 = 0; a2 < 3; a2++) {
#pragma unroll
        for (int d3 = 0; d3 < 10; d3++) {
          float s2 = att[a2][0] * vv[d3] + att[a2][1] * vv[10 + d3] + att[a2][2] * vv[20 + d3];
          int f = base + a2 * 10 + d3;
          int s = f / 100;
          int d = f - s * 100;
          Qw[s * LDA + d] = s2;
        }
      }
    }
    __syncthreads();

    // ---- O projection + residual -> sK ----
    stage_w(sW, SW_LDW, Wo_i, DM, DM, DM, 112);
    __syncthreads();
    {
      float acc[6][7];
#pragma unroll
      for (int r = 0; r < 6; r++)
#pragma unroll
        for (int c = 0; c < 7; c++) acc[r][c] = 0.f;
      gemm_acc<7>(sQ, LDA, sW, SW_LDW, DM, acc);
#pragma unroll
      for (int c = 0; c < 7; c++) {
        int n = tn + 16 * c;
        if (n < DM) {
          float bias = __ldg(bo_i + n);
#pragma unroll
          for (int r = 0; r < 6; r++) {
            int m = tm + 16 * r;
            sK[m * LDA + n] = acc[r][c] + bias + sX[m * LDA + n];
          }
        }
      }
    }
    __syncthreads();

    // ---- LayerNorm 1 -> sX ----
    layernorm_rows(sK, sX, ln1g + li * DM, ln1b + li * DM);
    __syncthreads();

    // ---- FFN: y = relu(X@W1^T + b1) @ W2^T, chunked over FF ----
    float yacc[6][7];
#pragma unroll
    for (int r = 0; r < 6; r++)
#pragma unroll
      for (int c = 0; c < 7; c++) yacc[r][c] = 0.f;

    for (int cc = 0; cc < FFD / FC; cc++) {
      // stage W1 chunk [FC][DM]
      stage_w(sW, SW_LDW, W1 + (size_t)li * FFD * DM + cc * FC * DM, DM, FC, DM, FC);
      __syncthreads();
      {
        float hacc[6][4];
#pragma unroll
        for (int r = 0; r < 6; r++)
#pragma unroll
          for (int c = 0; c < 4; c++) hacc[r][c] = 0.f;
        gemm_acc<4>(sX, LDA, sW, SW_LDW, DM, hacc);
        const float* b1c = b1 + li * FFD + cc * FC;
#pragma unroll
        for (int c = 0; c < 4; c++) {
          int n = tn + 16 * c;
          float bias = __ldg(b1c + n);
#pragma unroll
          for (int r = 0; r < 6; r++)
            sQ[(tm + 16 * r) * LDA + n] = fmaxf(hacc[r][c] + bias, 0.f);
        }
      }
      __syncthreads();
      // stage W2 chunk: sW[d][ffl] = W2[d][cc*FC + ffl]
      stage_w(sW, SW2_LDW, W2 + (size_t)li * DM * FFD + cc * FC, FFD, DM, FC, 112);
      __syncthreads();
      gemm_acc<7>(sQ, LDA, sW, SW2_LDW, FC, yacc);
      __syncthreads();
    }

    // ---- FFN bias + residual -> sK, then LayerNorm 2 -> sX ----
    {
      const float* b2i = b2 + li * DM;
#pragma unroll
      for (int c = 0; c < 7; c++) {
        int n = tn + 16 * c;
        if (n < DM) {
          float bias = __ldg(b2i + n);
#pragma unroll
          for (int r = 0; r < 6; r++) {
            int m = tm + 16 * r;
            sK[m * LDA + n] = yacc[r][c] + bias + sX[m * LDA + n];
          }
        }
      }
    }
    __syncthreads();
    layernorm_rows(sK, sX, ln2g + li * DM, ln2b + li * DM);
    __syncthreads();
  }

  // ---------------- classifier: out = flat(X)[300] @ Wf^T + bf ----------------
  stage_w(sW, WF_LDW, Wf, SD, NCLS, SD, NCLS);
  __syncthreads();
  for (int task = tid; task < TB * NCLS; task += THREADS) {
    int e = task / NCLS;
    int c = task - e * NCLS;
    const float* Xe = sX + 3 * e * LDA;
    const float* wr = sW + c * WF_LDW;
    float dot = __ldg(bf + c);
#pragma unroll
    for (int s = 0; s < 3; s++) {
#pragma unroll 4
      for (int d = 0; d < DM; d++)
        dot = fmaf(Xe[s * LDA + d], wr[s * DM + d], dot);
    }
    out[(blockIdx.x * TB + e) * NCLS + c] = dot;
  }
}

extern "C" void kernel_launch(void* const* d_in, const int* in_sizes, int n_in,
                              void* d_out, int out_size) {
  const float* x   = (const float*)d_in[0];
  // d_in[1] = label, d_in[2] = fa_label : unused by the forward pass
  const float* We  = (const float*)d_in[3];
  const float* be  = (const float*)d_in[4];
  const float* pe  = (const float*)d_in[5];
  const float* Wq  = (const float*)d_in[6];
  const float* bq  = (const float*)d_in[7];
  const float* Wk  = (const float*)d_in[8];
  const float* bk  = (const float*)d_in[9];
  const float* Wv  = (const float*)d_in[10];
  const float* bv  = (const float*)d_in[11];
  const float* Wo  = (const float*)d_in[12];
  const float* bo  = (const float*)d_in[13];
  const float* l1g = (const float*)d_in[14];
  const float* l1b = (const float*)d_in[15];
  const float* W1  = (const float*)d_in[16];
  const float* b1  = (const float*)d_in[17];
  const float* W2  = (const float*)d_in[18];
  const float* b2  = (const float*)d_in[19];
  const float* l2g = (const float*)d_in[20];
  const float* l2b = (const float*)d_in[21];
  const float* Wf  = (const float*)d_in[22];
  const float* bf  = (const float*)d_in[23];
  float* out = (float*)d_out;

  int Bsz = in_sizes[0] / (3 * DIN);       // 65536
  int nblocks = Bsz / TB;                  // 2048
  size_t smem = (size_t)SMEM_FLOATS * sizeof(float);  // 208,384 B

  cudaFuncSetAttribute(geomapnet_kernel,
                       cudaFuncAttributeMaxDynamicSharedMemorySize, (int)smem);
  geomapnet_kernel<<<nblocks, THREADS, smem>>>(x, We, be, pe, Wq, bq, Wk, bk, Wv, bv,
                                               Wo, bo, l1g, l1b, W1, b1, W2, b2,
                                               l2g, l2b, Wf, bf, out);
}

// round 3
// speedup vs baseline: 1.0797x; 1.0797x over previous
#include <cuda_runtime.h>

#define THREADS 512
#define TB 32          // batch elements per CTA
#define MROWS 96       // token rows per CTA (TB*3)
#define LDA 104        // smem row stride for activations (float4-aligned)
#define DM 100
#define DIN 72
#define FFD 512
#define FC 64          // FFN chunk
#define NLAYERS 8
#define NCLS 40
#define SD 300

#define OFF_X 0
#define OFF_Q 9984
#define OFF_K 19968
#define OFF_V 29952
#define OFF_W 39936
#define SMEM_FLOATS 52096   // 208,384 bytes dynamic smem

#define SW_LDW 108      // weight stride for K<=100 staged blocks (x4-aligned, conflict-free)
#define SW2_LDW 68      // weight stride for FC-col blocks
#define WF_LDW 304      // classifier weight stride (float2-aligned)

typedef unsigned long long ull;

__device__ __forceinline__ void ffma2(ull& acc, ull a, ull b) {
  asm("fma.rn.f32x2 %0, %1, %2, %0;" : "+l"(acc) : "l"(a), "l"(b));
}
__device__ __forceinline__ ull pack2(float x, float y) {
  ull r; asm("mov.b64 %0, {%1, %2};" : "=l"(r) : "f"(x), "f"(y)); return r;
}
__device__ __forceinline__ float sum2(ull v) {
  float lo, hi; asm("mov.b64 {%0, %1}, %2;" : "=f"(lo), "=f"(hi) : "l"(v));
  return lo + hi;
}

// Copy weight block (row-major [rows x cols]) into shared with row stride ldw,
// zero-padding rows up to prows.
__device__ __forceinline__ void stage_w(float* dst, int ldw, const float* __restrict__ src,
                                        int sstride, int rows, int cols, int prows) {
  const int total = prows * cols;
  for (int idx = threadIdx.x; idx < total; idx += THREADS) {
    int r = idx / cols;
    int c = idx - r * cols;
    dst[r * ldw + c] = (r < rows) ? src[r * sstride + c] : 0.0f;
  }
}

// C[m][n] += sum_k A[m][k] * W[n][k]
// 512 threads as 32(tm) x 16(tn); each thread owns rows {tm, tm+32, tm+64},
// cols {tn, tn+16, ...}. f32x2 packed accumulation, float4 shared loads.
template <int NC>
__device__ __forceinline__ void gemm_acc2(const float* __restrict__ A, int lda,
                                          const float* __restrict__ W, int ldw,
                                          int K, ull (&acc)[3][NC]) {
  const int tn = threadIdx.x & 15;
  const int tm = threadIdx.x >> 4;
  const float* a0 = A + tm * lda;
  const float* w0 = W + tn * ldw;
#pragma unroll 2
  for (int k = 0; k < K; k += 4) {
    float4 a4[3];
#pragma unroll
    for (int r = 0; r < 3; r++)
      a4[r] = *reinterpret_cast<const float4*>(a0 + r * 32 * lda + k);
    ull alo[3], ahi[3];
#pragma unroll
    for (int r = 0; r < 3; r++) { alo[r] = pack2(a4[r].x, a4[r].y); ahi[r] = pack2(a4[r].z, a4[r].w); }
#pragma unroll
    for (int c = 0; c < NC; c++) {
      float4 w4 = *reinterpret_cast<const float4*>(w0 + c * 16 * ldw + k);
      ull wlo = pack2(w4.x, w4.y), whi = pack2(w4.z, w4.w);
#pragma unroll
      for (int r = 0; r < 3; r++) {
        ffma2(acc[r][c], alo[r], wlo);
        ffma2(acc[r][c], ahi[r], whi);
      }
    }
  }
}

template <int NC>
__device__ __forceinline__ void zero_acc(ull (&acc)[3][NC]) {
#pragma unroll
  for (int r = 0; r < 3; r++)
#pragma unroll
    for (int c = 0; c < NC; c++) acc[r][c] = 0ull;
}

__device__ __forceinline__ void layernorm_rows(const float* __restrict__ src,
                                               float* __restrict__ dst,
                                               const float* __restrict__ g,
                                               const float* __restrict__ b) {
  const int tid = threadIdx.x;
  if (tid < MROWS) {
    const float* y = src + tid * LDA;
    float m = 0.f;
#pragma unroll 4
    for (int d = 0; d < DM; d++) m += y[d];
    m *= (1.0f / DM);
    float v = 0.f;
#pragma unroll 4
    for (int d = 0; d < DM; d++) { float t = y[d] - m; v = fmaf(t, t, v); }
    v *= (1.0f / DM);
    float inv = rsqrtf(v + 1e-5f);
    float* o = dst + tid * LDA;
#pragma unroll 4
    for (int d = 0; d < DM; d++)
      o[d] = (y[d] - m) * inv * __ldg(g + d) + __ldg(b + d);
  }
}

__global__ void __launch_bounds__(THREADS, 1)
geomapnet_kernel(const float* __restrict__ x,
                 const float* __restrict__ We, const float* __restrict__ be,
                 const float* __restrict__ pe,
                 const float* __restrict__ Wq, const float* __restrict__ bq,
                 const float* __restrict__ Wk, const float* __restrict__ bk,
                 const float* __restrict__ Wv, const float* __restrict__ bv,
                 const float* __restrict__ Wo, const float* __restrict__ bo,
                 const float* __restrict__ ln1g, const float* __restrict__ ln1b,
                 const float* __restrict__ W1, const float* __restrict__ b1,
                 const float* __restrict__ W2, const float* __restrict__ b2,
                 const float* __restrict__ ln2g, const float* __restrict__ ln2b,
                 const float* __restrict__ Wf, const float* __restrict__ bf,
                 float* __restrict__ out)
{
  extern __shared__ float smem[];
  float* sX = smem + OFF_X;   // [96][104] residual-stream activations
  float* sQ = smem + OFF_Q;   // [96][104] Q / ctx / FFN hidden chunk
  float* sK = smem + OFF_K;   // [96][104] K / pre-LN scratch
  float* sV = smem + OFF_V;   // [96][104] V
  float* sW = smem + OFF_W;   // weight staging, 12160 floats

  const int tid = threadIdx.x;
  const int tn = tid & 15;
  const int tm = tid >> 4;
  const int rowbase = blockIdx.x * MROWS;

  // ---------------- embedding: X = x @ We^T + be + pe ----------------
  for (int idx = tid; idx < MROWS * DIN; idx += THREADS) {
    int r = idx / DIN, c = idx - r * DIN;
    sQ[r * LDA + c] = x[(rowbase + r) * DIN + c];
  }
  stage_w(sW, SW_LDW, We, DIN, DM, DIN, 112);
  __syncthreads();
  {
    ull acc[3][7];
    zero_acc<7>(acc);
    gemm_acc2<7>(sQ, LDA, sW, SW_LDW, DIN, acc);
#pragma unroll
    for (int c = 0; c < 7; c++) {
      int n = tn + 16 * c;
      if (n < DM) {
        float bias = __ldg(be + n);
#pragma unroll
        for (int r = 0; r < 3; r++) {
          int m = tm + 32 * r;
          sX[m * LDA + n] = sum2(acc[r][c]) + bias + __ldg(pe + (m % 3) * DM + n);
        }
      }
    }
  }
  __syncthreads();

  // ---------------- encoder layers ----------------
  for (int li = 0; li < NLAYERS; li++) {
    const float* Wq_i = Wq + li * DM * DM;
    const float* Wk_i = Wk + li * DM * DM;
    const float* Wv_i = Wv + li * DM * DM;
    const float* Wo_i = Wo + li * DM * DM;
    const float* bq_i = bq + li * DM;
    const float* bk_i = bk + li * DM;
    const float* bv_i = bv + li * DM;
    const float* bo_i = bo + li * DM;

    // ---- Q projection ----
    stage_w(sW, SW_LDW, Wq_i, DM, DM, DM, 112);
    __syncthreads();
    {
      ull acc[3][7];
      zero_acc<7>(acc);
      gemm_acc2<7>(sX, LDA, sW, SW_LDW, DM, acc);
#pragma unroll
      for (int c = 0; c < 7; c++) {
        int n = tn + 16 * c;
        if (n < DM) {
          float bias = __ldg(bq_i + n);
#pragma unroll
          for (int r = 0; r < 3; r++) sQ[(tm + 32 * r) * LDA + n] = sum2(acc[r][c]) + bias;
        }
      }
    }
    __syncthreads();

    // ---- K projection ----
    stage_w(sW, SW_LDW, Wk_i, DM, DM, DM, 112);
    __syncthreads();
    {
      ull acc[3][7];
      zero_acc<7>(acc);
      gemm_acc2<7>(sX, LDA, sW, SW_LDW, DM, acc);
#pragma unroll
      for (int c = 0; c < 7; c++) {
        int n = tn + 16 * c;
        if (n < DM) {
          float bias = __ldg(bk_i + n);
#pragma unroll
          for (int r = 0; r < 3; r++) sK[(tm + 32 * r) * LDA + n] = sum2(acc[r][c]) + bias;
        }
      }
    }
    __syncthreads();

    // ---- V projection ----
    stage_w(sW, SW_LDW, Wv_i, DM, DM, DM, 112);
    __syncthreads();
    {
      ull acc[3][7];
      zero_acc<7>(acc);
      gemm_acc2<7>(sX, LDA, sW, SW_LDW, DM, acc);
#pragma unroll
      for (int c = 0; c < 7; c++) {
        int n = tn + 16 * c;
        if (n < DM) {
          float bias = __ldg(bv_i + n);
#pragma unroll
          for (int r = 0; r < 3; r++) sV[(tm + 32 * r) * LDA + n] = sum2(acc[r][c]) + bias;
        }
      }
    }
    __syncthreads();

    // ---- attention (flat row-major head split: head h = flat[h*30 .. h*30+30)) ----
    for (int task = tid; task < TB * 10; task += THREADS) {
      int e = task / 10;
      int h = task - e * 10;
      const int base = h * 30;
      const float* Qe = sQ + (3 * e) * LDA;
      const float* Ke = sK + (3 * e) * LDA;
      const float* Ve = sV + (3 * e) * LDA;
      // flat index f -> smem offset
      auto offf = [&](int f) { int s = f / 100; return s * LDA + (f - s * 100); };
      const float scale = 0.3162277660168379f;  // 10^-0.5
      // scores: q held per row, k streamed
      float att[3][3];
      float q[30];
#pragma unroll
      for (int j = 0; j < 30; j++) q[j] = Qe[offf(base + j)];
#pragma unroll
      for (int b2 = 0; b2 < 3; b2++) {
        float kk[10];
#pragma unroll
        for (int d3 = 0; d3 < 10; d3++) kk[d3] = Ke[offf(base + b2 * 10 + d3)];
#pragma unroll
        for (int a2 = 0; a2 < 3; a2++) {
          float s2 = 0.f;
#pragma unroll
          for (int d3 = 0; d3 < 10; d3++) s2 = fmaf(q[a2 * 10 + d3], kk[d3], s2);
          att[a2][b2] = s2 * scale;
        }
      }
#pragma unroll
      for (int a2 = 0; a2 < 3; a2++) {
        float mx = fmaxf(att[a2][0], fmaxf(att[a2][1], att[a2][2]));
        float sum = 0.f;
#pragma unroll
        for (int b2 = 0; b2 < 3; b2++) { att[a2][b2] = __expf(att[a2][b2] - mx); sum += att[a2][b2]; }
        float inv = 1.f / sum;
#pragma unroll
        for (int b2 = 0; b2 < 3; b2++) att[a2][b2] *= inv;
      }
      float* Qw = sQ + (3 * e) * LDA;
#pragma unroll
      for (int d3 = 0; d3 < 10; d3++) {
        float v0 = Ve[offf(base + d3)];
        float v1 = Ve[offf(base + 10 + d3)];
        float v2 = Ve[offf(base + 20 + d3)];
#pragma unroll
        for (int a2 = 0; a2 < 3; a2++) {
          float s2 = att[a2][0] * v0 + att[a2][1] * v1 + att[a2][2] * v2;
          Qw[offf(base + a2 * 10 + d3)] = s2;
        }
      }
    }
    __syncthreads();

    // ---- O projection + residual -> sK ----
    stage_w(sW, SW_LDW, Wo_i, DM, DM, DM, 112);
    __syncthreads();
    {
      ull acc[3][7];
      zero_acc<7>(acc);
      gemm_acc2<7>(sQ, LDA, sW, SW_LDW, DM, acc);
#pragma unroll
      for (int c = 0; c < 7; c++) {
        int n = tn + 16 * c;
        if (n < DM) {
          float bias = __ldg(bo_i + n);
#pragma unroll
          for (int r = 0; r < 3; r++) {
            int m = tm + 32 * r;
            sK[m * LDA + n] = sum2(acc[r][c]) + bias + sX[m * LDA + n];
          }
        }
      }
    }
    __syncthreads();

    // ---- LayerNorm 1 -> sX ----
    layernorm_rows(sK, sX, ln1g + li * DM, ln1b + li * DM);
    __syncthreads();

    // ---- FFN: y = relu(X@W1^T + b1) @ W2^T, chunked over FF ----
    ull yacc[3][7];
    zero_acc<7>(yacc);

    for (int cc = 0; cc < FFD / FC; cc++) {
      // stage W1 chunk [FC][DM]
      stage_w(sW, SW_LDW, W1 + (size_t)li * FFD * DM + cc * FC * DM, DM, FC, DM, FC);
      __syncthreads();
      {
        ull hacc[3][4];
        zero_acc<4>(hacc);
        gemm_acc2<4>(sX, LDA, sW, SW_LDW, DM, hacc);
        const float* b1c = b1 + li * FFD + cc * FC;
#pragma unroll
        for (int c = 0; c < 4; c++) {
          int n = tn + 16 * c;
          float bias = __ldg(b1c + n);
#pragma unroll
          for (int r = 0; r < 3; r++)
            sQ[(tm + 32 * r) * LDA + n] = fmaxf(sum2(hacc[r][c]) + bias, 0.f);
        }
      }
      __syncthreads();
      // stage W2 chunk: sW[d][ffl] = W2[d][cc*FC + ffl]
      stage_w(sW, SW2_LDW, W2 + (size_t)li * DM * FFD + cc * FC, FFD, DM, FC, 112);
      __syncthreads();
      gemm_acc2<7>(sQ, LDA, sW, SW2_LDW, FC, yacc);
      __syncthreads();
    }

    // ---- FFN bias + residual -> sK, then LayerNorm 2 -> sX ----
    {
      const float* b2i = b2 + li * DM;
#pragma unroll
      for (int c = 0; c < 7; c++) {
        int n = tn + 16 * c;
        if (n < DM) {
          float bias = __ldg(b2i + n);
#pragma unroll
          for (int r = 0; r < 3; r++) {
            int m = tm + 32 * r;
            sK[m * LDA + n] = sum2(yacc[r][c]) + bias + sX[m * LDA + n];
          }
        }
      }
    }
    __syncthreads();
    layernorm_rows(sK, sX, ln2g + li * DM, ln2b + li * DM);
    __syncthreads();
  }

  // ---------------- classifier: out = flat(X)[300] @ Wf^T + bf ----------------
  stage_w(sW, WF_LDW, Wf, SD, NCLS, SD, NCLS);
  __syncthreads();
  for (int task = tid; task < TB * NCLS; task += THREADS) {
    int e = task / NCLS;
    int c = task - e * NCLS;
    const float* Xe = sX + 3 * e * LDA;
    const float* wr = sW + c * WF_LDW;
    ull acc = 0ull;
#pragma unroll
    for (int s = 0; s < 3; s++) {
#pragma unroll 5
      for (int d = 0; d < DM; d += 2) {
        ffma2(acc, pack2(Xe[s * LDA + d], Xe[s * LDA + d + 1]),
                   pack2(wr[s * DM + d], wr[s * DM + d + 1]));
      }
    }
    out[(blockIdx.x * TB + e) * NCLS + c] = sum2(acc) + __ldg(bf + c);
  }
}

extern "C" void kernel_launch(void* const* d_in, const int* in_sizes, int n_in,
                              void* d_out, int out_size) {
  const float* x   = (const float*)d_in[0];
  // d_in[1] = label, d_in[2] = fa_label : unused by the forward pass
  const float* We  = (const float*)d_in[3];
  const float* be  = (const float*)d_in[4];
  const float* pe  = (const float*)d_in[5];
  const float* Wq  = (const float*)d_in[6];
  const float* bq  = (const float*)d_in[7];
  const float* Wk  = (const float*)d_in[8];
  const float* bk  = (const float*)d_in[9];
  const float* Wv  = (const float*)d_in[10];
  const float* bv  = (const float*)d_in[11];
  const float* Wo  = (const float*)d_in[12];
  const float* bo  = (const float*)d_in[13];
  const float* l1g = (const float*)d_in[14];
  const float* l1b = (const float*)d_in[15];
  const float* W1  = (const float*)d_in[16];
  const float* b1  = (const float*)d_in[17];
  const float* W2  = (const float*)d_in[18];
  const float* b2  = (const float*)d_in[19];
  const float* l2g = (const float*)d_in[20];
  const float* l2b = (const float*)d_in[21];
  const float* Wf  = (const float*)d_in[22];
  const float* bf  = (const float*)d_in[23];
  float* out = (float*)d_out;

  int Bsz = in_sizes[0] / (3 * DIN);       // 65536
  int nblocks = Bsz / TB;                  // 2048
  size_t smem = (size_t)SMEM_FLOATS * sizeof(float);  // 208,384 B

  cudaFuncSetAttribute(geomapnet_kernel,
                       cudaFuncAttributeMaxDynamicSharedMemorySize, (int)smem);
  geomapnet_kernel<<<nblocks, THREADS, smem>>>(x, We, be, pe, Wq, bq, Wk, bk, Wv, bv,
                                               Wo, bo, l1g, l1b, W1, b1, W2, b2,
                                               l2g, l2b, Wf, bf, out);
}